// round 4
// baseline (speedup 1.0000x reference)
#include <cuda_runtime.h>

typedef unsigned long long ull;

#define NSUP 25
#define CWH  3072
#define DF   640
#define MS   400
#define MQ   240
#define MKF  640
#define NRHS 16
#define SPLITS_KF 8

// ---------------- device scratch ----------------
__device__ __align__(16) float g_KF[MKF * DF];
__device__ __align__(16) float g_parts[SPLITS_KF * MKF * DF];
__device__ __align__(16) float g_aul[MS * MS];
__device__ __align__(16) float g_A2[MS * MS];
__device__ __align__(16) float g_Ba[MS * MS];
__device__ __align__(16) float g_Bb[MS * MS];
__device__ __align__(16) float g_Xa[MS * NRHS];
__device__ __align__(16) float g_Xb[MS * NRHS];
__device__ float g_red[128];
__device__ float g_scal[4];
__device__ __align__(16) float g_w[NRHS * DF];

// ---------------- packed f32x2 helpers ----------------
__device__ __forceinline__ ull ffma2(ull a, ull b, ull c) {
    ull d;
    asm("fma.rn.f32x2 %0, %1, %2, %3;" : "=l"(d) : "l"(a), "l"(b), "l"(c));
    return d;
}
union UF2 { float2 f; ull u; };
__device__ __forceinline__ ull dup2(float x) {
    UF2 t; t.f = make_float2(x, x); return t.u;
}
__device__ __forceinline__ float2 u2f(ull v) {
    UF2 t; t.u = v; return t.f;
}

// ============================================================
// GEMM KF: [S;Q](640x3072) @ W(3072x640) -> split-K partials
// BM=128 BN=64 BK=16, 128 threads, 8x8 micro (f32x2)
// ============================================================
__global__ __launch_bounds__(128) void k_gemm_kf(const float* __restrict__ S,
                                                 const float* __restrict__ Qm,
                                                 const float* __restrict__ W) {
    __shared__ float As[16][132];
    __shared__ float Bs[16][68];
    const int tid = threadIdx.x;
    const int n0 = blockIdx.x * 64;
    const int m0 = blockIdx.y * 128;
    const int sp = blockIdx.z;
    const int nkt = CWH / 16;
    const int kt0 = sp * nkt / SPLITS_KF, kt1 = (sp + 1) * nkt / SPLITS_KF;
    const int arow = m0 + tid;
    const float* Ap = (arow < MS) ? (S + (size_t)arow * CWH)
                                  : (Qm + (size_t)(arow - MS) * CWH);
    const int ty = tid >> 3, tx = tid & 7;
    ull acc[8][4];
#pragma unroll
    for (int i = 0; i < 8; i++)
#pragma unroll
        for (int u = 0; u < 4; u++) acc[i][u] = 0ull;

    for (int kt = kt0; kt < kt1; ++kt) {
        const int k0 = kt * 16;
#pragma unroll
        for (int q = 0; q < 4; q++) {
            float4 v = *reinterpret_cast<const float4*>(Ap + k0 + q * 4);
            As[q * 4 + 0][tid] = v.x; As[q * 4 + 1][tid] = v.y;
            As[q * 4 + 2][tid] = v.z; As[q * 4 + 3][tid] = v.w;
        }
#pragma unroll
        for (int i = 0; i < 2; i++) {
            int idx = tid + i * 128;
            int kk = idx >> 4, c4 = idx & 15;
            float4 v = *reinterpret_cast<const float4*>(W + (size_t)(k0 + kk) * DF + n0 + c4 * 4);
            *reinterpret_cast<float4*>(&Bs[kk][c4 * 4]) = v;
        }
        __syncthreads();
#pragma unroll
        for (int k = 0; k < 16; k++) {
            float av[8];
            *(float4*)&av[0] = *(float4*)&As[k][ty * 8];
            *(float4*)&av[4] = *(float4*)&As[k][ty * 8 + 4];
            ull bv[4];
#pragma unroll
            for (int u = 0; u < 4; u++)
                bv[u] = *reinterpret_cast<const ull*>(&Bs[k][tx * 8 + 2 * u]);
#pragma unroll
            for (int i = 0; i < 8; i++) {
                ull ai = dup2(av[i]);
#pragma unroll
                for (int u = 0; u < 4; u++) acc[i][u] = ffma2(ai, bv[u], acc[i][u]);
            }
        }
        __syncthreads();
    }
    float* out = g_parts + (size_t)sp * MKF * DF;
#pragma unroll
    for (int i = 0; i < 8; i++) {
        int r = m0 + ty * 8 + i;
#pragma unroll
        for (int u = 0; u < 4; u++)
            *reinterpret_cast<ull*>(out + (size_t)r * DF + n0 + tx * 8 + 2 * u) = acc[i][u];
    }
}

__global__ void k_reduce_kf() {
    int i = blockIdx.x * 256 + threadIdx.x;
    if (i >= MKF * DF) return;
    const size_t T = (size_t)MKF * DF;
    float s = 0.f;
#pragma unroll
    for (int p = 0; p < SPLITS_KF; p++) s += g_parts[p * T + i];
    g_KF[i] = s;
}

// ============================================================
// aul = K K^T + 50 I   (NT, 400x400x640) single pass
// BM=64 BN=32 BK=16, 128 thr, 8x2 micro (f32x2), grid (13,7)
// ============================================================
__global__ __launch_bounds__(128) void k_gemm_aul() {
    __shared__ float As[16][68];
    __shared__ float Bs[16][36];
    const int tid = threadIdx.x;
    const int n0 = blockIdx.x * 32;
    const int m0 = blockIdx.y * 64;
    const int ty = tid >> 4, tx = tid & 15;
    ull acc[8];
#pragma unroll
    for (int i = 0; i < 8; i++) acc[i] = 0ull;

    for (int kt = 0; kt < DF / 16; ++kt) {
        const int k0 = kt * 16;
#pragma unroll
        for (int i = 0; i < 2; i++) {
            int idx = tid + i * 128;
            int r = idx >> 2, q = idx & 3;
            int rr = m0 + r; if (rr >= MS) rr = MS - 1;
            float4 v = *reinterpret_cast<const float4*>(g_KF + (size_t)rr * DF + k0 + q * 4);
            As[q * 4 + 0][r] = v.x; As[q * 4 + 1][r] = v.y;
            As[q * 4 + 2][r] = v.z; As[q * 4 + 3][r] = v.w;
        }
        {
            int n = tid >> 2, q = tid & 3;
            int nn = n0 + n; if (nn >= MS) nn = MS - 1;
            float4 v = *reinterpret_cast<const float4*>(g_KF + (size_t)nn * DF + k0 + q * 4);
            Bs[q * 4 + 0][n] = v.x; Bs[q * 4 + 1][n] = v.y;
            Bs[q * 4 + 2][n] = v.z; Bs[q * 4 + 3][n] = v.w;
        }
        __syncthreads();
#pragma unroll
        for (int k = 0; k < 16; k++) {
            float av[8];
            *(float4*)&av[0] = *(float4*)&As[k][ty * 8];
            *(float4*)&av[4] = *(float4*)&As[k][ty * 8 + 4];
            ull bv = *reinterpret_cast<const ull*>(&Bs[k][tx * 2]);
#pragma unroll
            for (int i = 0; i < 8; i++) acc[i] = ffma2(dup2(av[i]), bv, acc[i]);
        }
        __syncthreads();
    }
    int c = n0 + tx * 2;
    if (c < MS) {
#pragma unroll
        for (int i = 0; i < 8; i++) {
            int r = m0 + ty * 8 + i;
            if (r < MS) {
                float2 f = u2f(acc[i]);
                if (r == c) f.x += 50.0f;
                if (r == c + 1) f.y += 50.0f;
                UF2 t; t.f = f;
                *reinterpret_cast<ull*>(g_aul + (size_t)r * MS + c) = t.u;
            }
        }
    }
}

// ============================================================
// A2 = aul @ aul (NN, 400x400x400) + fused Frobenius^2 partials
// ============================================================
__global__ __launch_bounds__(128) void k_gemm_a2() {
    __shared__ float As[16][68];
    __shared__ float Bs[16][36];
    const int tid = threadIdx.x;
    const int n0 = blockIdx.x * 32;
    const int m0 = blockIdx.y * 64;
    const int ty = tid >> 4, tx = tid & 15;
    ull acc[8];
#pragma unroll
    for (int i = 0; i < 8; i++) acc[i] = 0ull;

    for (int kt = 0; kt < MS / 16; ++kt) {
        const int k0 = kt * 16;
#pragma unroll
        for (int i = 0; i < 2; i++) {
            int idx = tid + i * 128;
            int r = idx >> 2, q = idx & 3;
            int rr = m0 + r; if (rr >= MS) rr = MS - 1;
            float4 v = *reinterpret_cast<const float4*>(g_aul + (size_t)rr * MS + k0 + q * 4);
            As[q * 4 + 0][r] = v.x; As[q * 4 + 1][r] = v.y;
            As[q * 4 + 2][r] = v.z; As[q * 4 + 3][r] = v.w;
        }
        {
            int kk = tid >> 3, c4 = tid & 7;
            int c = n0 + c4 * 4;
            float4 v = make_float4(0.f, 0.f, 0.f, 0.f);
            if (c < MS) v = *reinterpret_cast<const float4*>(g_aul + (size_t)(k0 + kk) * MS + c);
            *reinterpret_cast<float4*>(&Bs[kk][c4 * 4]) = v;
        }
        __syncthreads();
#pragma unroll
        for (int k = 0; k < 16; k++) {
            float av[8];
            *(float4*)&av[0] = *(float4*)&As[k][ty * 8];
            *(float4*)&av[4] = *(float4*)&As[k][ty * 8 + 4];
            ull bv = *reinterpret_cast<const ull*>(&Bs[k][tx * 2]);
#pragma unroll
            for (int i = 0; i < 8; i++) acc[i] = ffma2(dup2(av[i]), bv, acc[i]);
        }
        __syncthreads();
    }
    float fs = 0.f;
    int c = n0 + tx * 2;
    if (c < MS) {
#pragma unroll
        for (int i = 0; i < 8; i++) {
            int r = m0 + ty * 8 + i;
            if (r < MS) {
                float2 f = u2f(acc[i]);
                *reinterpret_cast<ull*>(g_A2 + (size_t)r * MS + c) = acc[i];
                fs += f.x * f.x + f.y * f.y;
            }
        }
    }
    __shared__ float red[128];
    red[tid] = fs; __syncthreads();
    for (int o = 64; o > 0; o >>= 1) {
        if (tid < o) red[tid] += red[tid + o];
        __syncthreads();
    }
    if (tid == 0) g_red[blockIdx.y * 13 + blockIdx.x] = red[0];
}

// b = ||A2||_F^(1/2) >= lambda_max(aul)
__global__ void k_f2_final() {
    __shared__ float sh[128];
    int tid = threadIdx.x;
    sh[tid] = (tid < 91) ? g_red[tid] : 0.f;
    __syncthreads();
    for (int o = 64; o > 0; o >>= 1) {
        if (tid < o) sh[tid] += sh[tid + o];
        __syncthreads();
    }
    if (tid == 0) {
        float b = sqrtf(sqrtf(sh[0])) * 1.0001f;
        if (!(b > 51.f)) b = 51.f;
        g_scal[0] = b;
        g_scal[1] = 1.0f / b;
    }
}

// B = I - A/b ; B^2 = I - 2A/b + A2/b^2 ; X1 = 2P - (1/b)*rowblocksum(aul)
__global__ void k_buildBX() {
    int i = blockIdx.x * 256 + threadIdx.x;
    float ib = g_scal[1];
    if (i < MS * MS) {
        int r = i / MS, c = i - r * MS;
        float a = g_aul[i] * ib;
        float a2 = g_A2[i] * ib * ib;
        float d = (r == c) ? 1.f : 0.f;
        g_Ba[i] = d - a;
        g_Bb[i] = d - 2.f * a + a2;
    } else if (i < MS * MS + MS * NRHS) {
        int idx = i - MS * MS;
        int j = idx >> 4, c = idx & 15;
        float s = ((j / NSUP) == c) ? 2.f : 0.f;
        const float* row = g_aul + (size_t)j * MS + c * NSUP;
        float t = 0.f;
#pragma unroll
        for (int u = 0; u < NSUP; u++) t += row[u];
        g_Xa[idx] = s - t * ib;
    }
}

// ============================================================
// Fused iteration: [Bnext | X+=] = Bcur @ [Bcur | Xin] (400x416x400)
// BM=64 BN=32, grid (13,7), single launch, f32x2
// ============================================================
__global__ __launch_bounds__(128) void k_gemm_iter(int sel) {
    const float* __restrict__ Bc = sel ? g_Bb : g_Ba;
    const float* __restrict__ Xi = sel ? g_Xa : g_Xb;
    __shared__ float As[16][68];
    __shared__ float Bs[16][36];
    const int tid = threadIdx.x;
    const int n0 = blockIdx.x * 32;
    const int m0 = blockIdx.y * 64;
    const int ty = tid >> 4, tx = tid & 15;
    ull acc[8];
#pragma unroll
    for (int i = 0; i < 8; i++) acc[i] = 0ull;

    for (int kt = 0; kt < MS / 16; ++kt) {
        const int k0 = kt * 16;
#pragma unroll
        for (int i = 0; i < 2; i++) {
            int idx = tid + i * 128;
            int r = idx >> 2, q = idx & 3;
            int rr = m0 + r; if (rr >= MS) rr = MS - 1;
            float4 v = *reinterpret_cast<const float4*>(Bc + (size_t)rr * MS + k0 + q * 4);
            As[q * 4 + 0][r] = v.x; As[q * 4 + 1][r] = v.y;
            As[q * 4 + 2][r] = v.z; As[q * 4 + 3][r] = v.w;
        }
        {
            int kk = tid >> 3, c4 = tid & 7;
            int c = n0 + c4 * 4;
            float4 v;
            if (c < MS) v = *reinterpret_cast<const float4*>(Bc + (size_t)(k0 + kk) * MS + c);
            else v = *reinterpret_cast<const float4*>(Xi + (size_t)(k0 + kk) * NRHS + (c - MS));
            *reinterpret_cast<float4*>(&Bs[kk][c4 * 4]) = v;
        }
        __syncthreads();
#pragma unroll
        for (int k = 0; k < 16; k++) {
            float av[8];
            *(float4*)&av[0] = *(float4*)&As[k][ty * 8];
            *(float4*)&av[4] = *(float4*)&As[k][ty * 8 + 4];
            ull bv = *reinterpret_cast<const ull*>(&Bs[k][tx * 2]);
#pragma unroll
            for (int i = 0; i < 8; i++) acc[i] = ffma2(dup2(av[i]), bv, acc[i]);
        }
        __syncthreads();
    }
    float* Bn = sel ? g_Ba : g_Bb;
    float* Xo = sel ? g_Xb : g_Xa;
    int c = n0 + tx * 2;
#pragma unroll
    for (int i = 0; i < 8; i++) {
        int r = m0 + ty * 8 + i;
        if (r < MS) {
            if (c < MS) {
                *reinterpret_cast<ull*>(Bn + (size_t)r * MS + c) = acc[i];
            } else {
                float2 f = u2f(acc[i]);
                int xc = c - MS;
                Xo[r * NRHS + xc]     = Xi[r * NRHS + xc]     + f.x;
                Xo[r * NRHS + xc + 1] = Xi[r * NRHS + xc + 1] + f.y;
            }
        }
    }
}

// Final factor: Xa = Xb + B^1024 @ Xb   (B^1024 in g_Ba)
__global__ void k_xonly() {
    int idx = blockIdx.x * blockDim.x + threadIdx.x;
    if (idx >= MS * NRHS) return;
    int j = idx >> 4, c = idx & 15;
    const float* br = g_Ba + (size_t)j * MS;
    float s = g_Xb[idx];
#pragma unroll 4
    for (int k = 0; k < MS; k++) s = fmaf(br[k], g_Xb[k * NRHS + c], s);
    g_Xa[idx] = s;
}

// w[c][d] = (1/b) * sum_j Xa[j][c] * K[j][d]
__global__ void k_w() {
    int idx = blockIdx.x * 256 + threadIdx.x;
    if (idx >= NRHS * DF) return;
    int c = idx / DF, d = idx - c * DF;
    float s = 0.f;
#pragma unroll 4
    for (int j = 0; j < MS; j++) s = fmaf(g_Xa[j * NRHS + c], g_KF[(size_t)j * DF + d], s);
    g_w[idx] = s * g_scal[1];
}

// logits[q][c] = -gamma * sum_d f_x[q][d] * w[c][d]
__global__ void k_logits(float* __restrict__ out, const float* __restrict__ gamma) {
    int idx = blockIdx.x * 256 + threadIdx.x;
    if (idx >= MQ * 16) return;
    int q = idx >> 4, c = idx & 15;
    const float4* f = reinterpret_cast<const float4*>(g_KF + (size_t)(MS + q) * DF);
    const float4* wr = reinterpret_cast<const float4*>(g_w + (size_t)c * DF);
    float s = 0.f;
#pragma unroll 4
    for (int d = 0; d < DF / 4; d++) {
        float4 a = f[d], b = wr[d];
        s = fmaf(a.x, b.x, s); s = fmaf(a.y, b.y, s);
        s = fmaf(a.z, b.z, s); s = fmaf(a.w, b.w, s);
    }
    out[idx] = -gamma[0] * s;
}

// ============================================================
extern "C" void kernel_launch(void* const* d_in, const int* in_sizes, int n_in,
                              void* d_out, int out_size) {
    const float* S = (const float*)d_in[0];
    const float* Qm = (const float*)d_in[1];
    const float* W = (const float*)d_in[2];
    const float* gamma = (const float*)d_in[3];
    float* out = (float*)d_out;
    (void)in_sizes; (void)n_in; (void)out_size;

    k_gemm_kf<<<dim3(10, 5, SPLITS_KF), 128>>>(S, Qm, W);
    k_reduce_kf<<<(MKF * DF + 255) / 256, 256>>>();
    k_gemm_aul<<<dim3(13, 7), 128>>>();
    k_gemm_a2<<<dim3(13, 7), 128>>>();
    k_f2_final<<<1, 128>>>();
    k_buildBX<<<(MS * MS + MS * NRHS + 255) / 256, 256>>>();
    int sel = 1;
    for (int j = 1; j <= 9; j++) {
        k_gemm_iter<<<dim3(13, 7), 128>>>(sel);
        sel ^= 1;
    }
    k_xonly<<<(MS * NRHS + 255) / 256, 256>>>();
    k_w<<<(NRHS * DF + 255) / 256, 256>>>();
    k_logits<<<(MQ * 16 + 255) / 256, 256>>>(out, gamma);
}

// round 6
// speedup vs baseline: 1.3061x; 1.3061x over previous
#include <cuda_runtime.h>

typedef unsigned long long ull;

#define NSUP 25
#define CWH  3072
#define DF   640
#define MS   400
#define MQ   240
#define MKF  640
#define NRHS 16
#define CW   416          // concat width: 400 B cols + 16 X cols
#define SPLITS_KF 8

// ---------------- device scratch ----------------
__device__ __align__(16) float g_KF[MKF * DF];
__device__ __align__(16) float g_parts[SPLITS_KF * MKF * DF];
__device__ __align__(16) float g_aul[MS * MS];
__device__ __align__(16) float g_A2[MS * MS];
__device__ __align__(16) float g_Ba[MS * MS];      // later: dense B^1024
__device__ __align__(16) float g_Bb[MS * MS];      // B^2
__device__ __align__(16) float g_Xa[MS * NRHS];
__device__ __align__(16) float g_Xb[MS * NRHS];
__device__ __align__(16) float g_M[2][4][MS * CW]; // chain ping/pong, 4 K-splits
__device__ float g_red[128];
__device__ float g_scal[4];
__device__ __align__(16) float g_w[NRHS * DF];

// ---------------- packed f32x2 helpers ----------------
__device__ __forceinline__ ull ffma2(ull a, ull b, ull c) {
    ull d;
    asm("fma.rn.f32x2 %0, %1, %2, %3;" : "=l"(d) : "l"(a), "l"(b), "l"(c));
    return d;
}
union UF2 { float2 f; ull u; float s[2]; };
__device__ __forceinline__ ull pack2(float x, float y) {
    UF2 t; t.f = make_float2(x, y); return t.u;
}
__device__ __forceinline__ float2 u2f(ull v) { UF2 t; t.u = v; return t.f; }

// ============================================================
// GEMM KF: [S;Q](640x3072) @ W(3072x640) -> split-K partials
// (pipe-bound; unchanged structure)
// ============================================================
__global__ __launch_bounds__(128) void k_gemm_kf(const float* __restrict__ S,
                                                 const float* __restrict__ Qm,
                                                 const float* __restrict__ W) {
    __shared__ float As[16][132];
    __shared__ float Bs[16][68];
    const int tid = threadIdx.x;
    const int n0 = blockIdx.x * 64;
    const int m0 = blockIdx.y * 128;
    const int sp = blockIdx.z;
    const int nkt = CWH / 16;
    const int kt0 = sp * nkt / SPLITS_KF, kt1 = (sp + 1) * nkt / SPLITS_KF;
    const int arow = m0 + tid;
    const float* Ap = (arow < MS) ? (S + (size_t)arow * CWH)
                                  : (Qm + (size_t)(arow - MS) * CWH);
    const int ty = tid >> 3, tx = tid & 7;
    ull acc[8][4];
#pragma unroll
    for (int i = 0; i < 8; i++)
#pragma unroll
        for (int u = 0; u < 4; u++) acc[i][u] = 0ull;

    for (int kt = kt0; kt < kt1; ++kt) {
        const int k0 = kt * 16;
#pragma unroll
        for (int q = 0; q < 4; q++) {
            float4 v = *reinterpret_cast<const float4*>(Ap + k0 + q * 4);
            As[q * 4 + 0][tid] = v.x; As[q * 4 + 1][tid] = v.y;
            As[q * 4 + 2][tid] = v.z; As[q * 4 + 3][tid] = v.w;
        }
#pragma unroll
        for (int i = 0; i < 2; i++) {
            int idx = tid + i * 128;
            int kk = idx >> 4, c4 = idx & 15;
            float4 v = *reinterpret_cast<const float4*>(W + (size_t)(k0 + kk) * DF + n0 + c4 * 4);
            *reinterpret_cast<float4*>(&Bs[kk][c4 * 4]) = v;
        }
        __syncthreads();
#pragma unroll
        for (int k = 0; k < 16; k++) {
            float av[8];
            *(float4*)&av[0] = *(float4*)&As[k][ty * 8];
            *(float4*)&av[4] = *(float4*)&As[k][ty * 8 + 4];
            ull bv[4];
#pragma unroll
            for (int u = 0; u < 4; u++)
                bv[u] = *reinterpret_cast<const ull*>(&Bs[k][tx * 8 + 2 * u]);
#pragma unroll
            for (int i = 0; i < 8; i++) {
                ull ai = pack2(av[i], av[i]);
#pragma unroll
                for (int u = 0; u < 4; u++) acc[i][u] = ffma2(ai, bv[u], acc[i][u]);
            }
        }
        __syncthreads();
    }
    float* out = g_parts + (size_t)sp * MKF * DF;
#pragma unroll
    for (int i = 0; i < 8; i++) {
        int r = m0 + ty * 8 + i;
#pragma unroll
        for (int u = 0; u < 4; u++)
            *reinterpret_cast<ull*>(out + (size_t)r * DF + n0 + tx * 8 + 2 * u) = acc[i][u];
    }
}

__global__ void k_reduce_kf() {
    int i = blockIdx.x * 256 + threadIdx.x;
    if (i >= MKF * DF) return;
    const size_t T = (size_t)MKF * DF;
    float s = 0.f;
#pragma unroll
    for (int p = 0; p < SPLITS_KF; p++) s += g_parts[p * T + i];
    g_KF[i] = s;
}

// ============================================================
// Lean micro-kernel GEMMs: BM=64 BN=32, 128 thr
// inner loop: 2 LDS.128 (A row-pairs) + 1 LDS.128 (B dup) + 8 FFMA2
// ============================================================

// aul = K K^T + 50 I   (NT, 400x400x640), grid (13,7)
__global__ __launch_bounds__(128) void k_gemm_aul() {
    __shared__ float As[16][68];
    __shared__ float Bs2[16][72];
    const int tid = threadIdx.x;
    const int n0 = blockIdx.x * 32;
    const int m0 = blockIdx.y * 64;
    const int ty = tid >> 4, tx = tid & 15;
    ull acc[4][2];
#pragma unroll
    for (int i = 0; i < 4; i++) { acc[i][0] = 0ull; acc[i][1] = 0ull; }

    for (int kt = 0; kt < DF / 16; ++kt) {
        const int k0 = kt * 16;
#pragma unroll
        for (int i = 0; i < 2; i++) {
            int idx = tid + i * 128;
            int r = idx >> 2, q = idx & 3;
            int rr = m0 + r; if (rr > MS - 1) rr = MS - 1;
            float4 v = *reinterpret_cast<const float4*>(g_KF + (size_t)rr * DF + k0 + q * 4);
            As[q * 4 + 0][r] = v.x; As[q * 4 + 1][r] = v.y;
            As[q * 4 + 2][r] = v.z; As[q * 4 + 3][r] = v.w;
        }
        {
            int n = tid >> 2, q = tid & 3;
            int nn = n0 + n; if (nn > MS - 1) nn = MS - 1;
            float4 v = *reinterpret_cast<const float4*>(g_KF + (size_t)nn * DF + k0 + q * 4);
            *reinterpret_cast<ull*>(&Bs2[q * 4 + 0][n * 2]) = pack2(v.x, v.x);
            *reinterpret_cast<ull*>(&Bs2[q * 4 + 1][n * 2]) = pack2(v.y, v.y);
            *reinterpret_cast<ull*>(&Bs2[q * 4 + 2][n * 2]) = pack2(v.z, v.z);
            *reinterpret_cast<ull*>(&Bs2[q * 4 + 3][n * 2]) = pack2(v.w, v.w);
        }
        __syncthreads();
#pragma unroll
        for (int k = 0; k < 16; k++) {
            float4 a0 = *(const float4*)&As[k][ty * 8];
            float4 a1 = *(const float4*)&As[k][ty * 8 + 4];
            float4 bq = *(const float4*)&Bs2[k][tx * 4];
            ull ap[4] = { pack2(a0.x, a0.y), pack2(a0.z, a0.w),
                          pack2(a1.x, a1.y), pack2(a1.z, a1.w) };
            ull b0 = pack2(bq.x, bq.y), b1 = pack2(bq.z, bq.w);
#pragma unroll
            for (int i = 0; i < 4; i++) {
                acc[i][0] = ffma2(ap[i], b0, acc[i][0]);
                acc[i][1] = ffma2(ap[i], b1, acc[i][1]);
            }
        }
        __syncthreads();
    }
    int c = n0 + tx * 2;
    if (c < MS) {
#pragma unroll
        for (int i = 0; i < 4; i++) {
            int r0 = m0 + ty * 8 + 2 * i;
            if (r0 < MS) {
                float2 f0 = u2f(acc[i][0]);   // (out[r0][c], out[r0+1][c])
                float2 f1 = u2f(acc[i][1]);   // (out[r0][c+1], out[r0+1][c+1])
                float x00 = f0.x, x10 = f0.y, x01 = f1.x, x11 = f1.y;
                if (r0 == c) x00 += 50.f;
                if (r0 == c + 1) x01 += 50.f;
                if (r0 + 1 == c) x10 += 50.f;
                if (r0 + 1 == c + 1) x11 += 50.f;
                *reinterpret_cast<ull*>(g_aul + (size_t)r0 * MS + c) = pack2(x00, x01);
                *reinterpret_cast<ull*>(g_aul + (size_t)(r0 + 1) * MS + c) = pack2(x10, x11);
            }
        }
    }
}

// A2 = aul @ aul (NN, 400x400x400) + fused Frobenius^2 partials, grid (13,7)
__global__ __launch_bounds__(128) void k_gemm_a2() {
    __shared__ float As[16][68];
    __shared__ float Bs2[16][72];
    const int tid = threadIdx.x;
    const int n0 = blockIdx.x * 32;
    const int m0 = blockIdx.y * 64;
    const int ty = tid >> 4, tx = tid & 15;
    ull acc[4][2];
#pragma unroll
    for (int i = 0; i < 4; i++) { acc[i][0] = 0ull; acc[i][1] = 0ull; }

    for (int kt = 0; kt < MS / 16; ++kt) {
        const int k0 = kt * 16;
#pragma unroll
        for (int i = 0; i < 2; i++) {
            int idx = tid + i * 128;
            int r = idx >> 2, q = idx & 3;
            int rr = m0 + r; if (rr > MS - 1) rr = MS - 1;
            float4 v = *reinterpret_cast<const float4*>(g_aul + (size_t)rr * MS + k0 + q * 4);
            As[q * 4 + 0][r] = v.x; As[q * 4 + 1][r] = v.y;
            As[q * 4 + 2][r] = v.z; As[q * 4 + 3][r] = v.w;
        }
        {
            int kk = tid >> 3, c4 = tid & 7;
            int c = n0 + c4 * 4;
            float4 v = make_float4(0.f, 0.f, 0.f, 0.f);
            if (c < MS) v = *reinterpret_cast<const float4*>(g_aul + (size_t)(k0 + kk) * MS + c);
            *reinterpret_cast<float4*>(&Bs2[kk][c4 * 8]) = make_float4(v.x, v.x, v.y, v.y);
            *reinterpret_cast<float4*>(&Bs2[kk][c4 * 8 + 4]) = make_float4(v.z, v.z, v.w, v.w);
        }
        __syncthreads();
#pragma unroll
        for (int k = 0; k < 16; k++) {
            float4 a0 = *(const float4*)&As[k][ty * 8];
            float4 a1 = *(const float4*)&As[k][ty * 8 + 4];
            float4 bq = *(const float4*)&Bs2[k][tx * 4];
            ull ap[4] = { pack2(a0.x, a0.y), pack2(a0.z, a0.w),
                          pack2(a1.x, a1.y), pack2(a1.z, a1.w) };
            ull b0 = pack2(bq.x, bq.y), b1 = pack2(bq.z, bq.w);
#pragma unroll
            for (int i = 0; i < 4; i++) {
                acc[i][0] = ffma2(ap[i], b0, acc[i][0]);
                acc[i][1] = ffma2(ap[i], b1, acc[i][1]);
            }
        }
        __syncthreads();
    }
    float fs = 0.f;
    int c = n0 + tx * 2;
    if (c < MS) {
#pragma unroll
        for (int i = 0; i < 4; i++) {
            int r0 = m0 + ty * 8 + 2 * i;
            if (r0 < MS) {
                float2 f0 = u2f(acc[i][0]);
                float2 f1 = u2f(acc[i][1]);
                *reinterpret_cast<ull*>(g_A2 + (size_t)r0 * MS + c) = pack2(f0.x, f1.x);
                *reinterpret_cast<ull*>(g_A2 + (size_t)(r0 + 1) * MS + c) = pack2(f0.y, f1.y);
                fs += f0.x * f0.x + f1.x * f1.x + f0.y * f0.y + f1.y * f1.y;
            }
        }
    }
    __shared__ float red[128];
    red[tid] = fs; __syncthreads();
    for (int o = 64; o > 0; o >>= 1) {
        if (tid < o) red[tid] += red[tid + o];
        __syncthreads();
    }
    if (tid == 0) g_red[blockIdx.y * 13 + blockIdx.x] = red[0];
}

// b = ||A2||_F^(1/2) >= lambda_max(aul)
__global__ void k_f2_final() {
    __shared__ float sh[128];
    int tid = threadIdx.x;
    sh[tid] = (tid < 91) ? g_red[tid] : 0.f;
    __syncthreads();
    for (int o = 64; o > 0; o >>= 1) {
        if (tid < o) sh[tid] += sh[tid + o];
        __syncthreads();
    }
    if (tid == 0) {
        float b = sqrtf(sqrtf(sh[0])) * 1.0001f;
        if (!(b > 51.f)) b = 51.f;
        g_scal[0] = b;
        g_scal[1] = 1.0f / b;
    }
}

// B^2 = I - 2A/b + A2/b^2 ; X1 = 2P - (1/b)*rowblocksum(aul)
__global__ void k_buildBX() {
    int i = blockIdx.x * 256 + threadIdx.x;
    float ib = g_scal[1];
    if (i < MS * MS) {
        int r = i / MS, c = i - r * MS;
        float a = g_aul[i] * ib;
        float a2 = g_A2[i] * ib * ib;
        float d = (r == c) ? 1.f : 0.f;
        g_Bb[i] = d - 2.f * a + a2;
    } else if (i < MS * MS + MS * NRHS) {
        int idx = i - MS * MS;
        int j = idx >> 4, c = idx & 15;
        float s = ((j / NSUP) == c) ? 2.f : 0.f;
        const float* row = g_aul + (size_t)j * MS + c * NSUP;
        float t = 0.f;
#pragma unroll
        for (int u = 0; u < NSUP; u++) t += row[u];
        g_Xa[idx] = s - t * ib;
    }
}

// ============================================================
// Chain iteration, split-K=4, partial in / partial out.
// M = [B (400x400) | X (400x16)] as 400x416; out = Bc @ M (+ [0|Xi] on sp 0)
// grid (13,7,4), 128 thr
// ============================================================
__global__ __launch_bounds__(128) void k_iter(int first, int src, int dst) {
    __shared__ float As[16][68];
    __shared__ float Bs2[16][72];
    const int tid = threadIdx.x;
    const int n0 = blockIdx.x * 32;
    const int m0 = blockIdx.y * 64;
    const int sp = blockIdx.z;
    const int kt0 = sp * 25 / 4, kt1 = (sp + 1) * 25 / 4;
    const int ty = tid >> 4, tx = tid & 15;
    const float* __restrict__ Ms = g_M[src][0];
    const int PS = MS * CW;   // per-split stride
    ull acc[4][2];
#pragma unroll
    for (int i = 0; i < 4; i++) { acc[i][0] = 0ull; acc[i][1] = 0ull; }

    for (int kt = kt0; kt < kt1; ++kt) {
        const int k0 = kt * 16;
        // A tile: rows m0..m0+63, B-region cols k0..k0+15
#pragma unroll
        for (int i = 0; i < 2; i++) {
            int idx = tid + i * 128;
            int r = idx >> 2, q = idx & 3;
            int rr = m0 + r; if (rr > MS - 1) rr = MS - 1;
            float4 v;
            if (first) {
                v = *reinterpret_cast<const float4*>(g_Bb + (size_t)rr * MS + k0 + q * 4);
            } else {
                const float* base = Ms + (size_t)rr * CW + k0 + q * 4;
                float4 v0 = *(const float4*)(base);
                float4 v1 = *(const float4*)(base + PS);
                float4 v2 = *(const float4*)(base + 2 * PS);
                float4 v3 = *(const float4*)(base + 3 * PS);
                v = make_float4(v0.x + v1.x + v2.x + v3.x, v0.y + v1.y + v2.y + v3.y,
                                v0.z + v1.z + v2.z + v3.z, v0.w + v1.w + v2.w + v3.w);
            }
            As[q * 4 + 0][r] = v.x; As[q * 4 + 1][r] = v.y;
            As[q * 4 + 2][r] = v.z; As[q * 4 + 3][r] = v.w;
        }
        // B tile: concat-M rows k0..k0+15, cols n0..n0+31 (dup-stored)
        {
            int kk = tid >> 3, c4 = tid & 7;
            int c = n0 + c4 * 4;
            int kr = k0 + kk;
            float4 v;
            if (first) {
                if (c < MS) v = *reinterpret_cast<const float4*>(g_Bb + (size_t)kr * MS + c);
                else        v = *reinterpret_cast<const float4*>(g_Xa + (size_t)kr * NRHS + (c - MS));
            } else {
                const float* base = Ms + (size_t)kr * CW + c;
                float4 v0 = *(const float4*)(base);
                float4 v1 = *(const float4*)(base + PS);
                float4 v2 = *(const float4*)(base + 2 * PS);
                float4 v3 = *(const float4*)(base + 3 * PS);
                v = make_float4(v0.x + v1.x + v2.x + v3.x, v0.y + v1.y + v2.y + v3.y,
                                v0.z + v1.z + v2.z + v3.z, v0.w + v1.w + v2.w + v3.w);
            }
            *reinterpret_cast<float4*>(&Bs2[kk][c4 * 8]) = make_float4(v.x, v.x, v.y, v.y);
            *reinterpret_cast<float4*>(&Bs2[kk][c4 * 8 + 4]) = make_float4(v.z, v.z, v.w, v.w);
        }
        __syncthreads();
#pragma unroll
        for (int k = 0; k < 16; k++) {
            float4 a0 = *(const float4*)&As[k][ty * 8];
            float4 a1 = *(const float4*)&As[k][ty * 8 + 4];
            float4 bq = *(const float4*)&Bs2[k][tx * 4];
            ull ap[4] = { pack2(a0.x, a0.y), pack2(a0.z, a0.w),
                          pack2(a1.x, a1.y), pack2(a1.z, a1.w) };
            ull b0 = pack2(bq.x, bq.y), b1 = pack2(bq.z, bq.w);
#pragma unroll
            for (int i = 0; i < 4; i++) {
                acc[i][0] = ffma2(ap[i], b0, acc[i][0]);
                acc[i][1] = ffma2(ap[i], b1, acc[i][1]);
            }
        }
        __syncthreads();
    }
    // epilogue
    float* __restrict__ outp = g_M[dst][sp];
    int c = n0 + tx * 2;
#pragma unroll
    for (int i = 0; i < 4; i++) {
        int r0 = m0 + ty * 8 + 2 * i;
        if (r0 < MS) {
            float2 f0 = u2f(acc[i][0]);   // (out[r0][c], out[r0+1][c])
            float2 f1 = u2f(acc[i][1]);   // (out[r0][c+1], out[r0+1][c+1])
            float x00 = f0.x, x10 = f0.y, x01 = f1.x, x11 = f1.y;
            if (sp == 0 && c >= MS) {
                // add Xi for the identity term of (I + B^2^j)
                if (first) {
                    x00 += g_Xa[r0 * NRHS + (c - MS)];
                    x01 += g_Xa[r0 * NRHS + (c - MS) + 1];
                    x10 += g_Xa[(r0 + 1) * NRHS + (c - MS)];
                    x11 += g_Xa[(r0 + 1) * NRHS + (c - MS) + 1];
                } else {
                    const float* b0p = Ms + (size_t)r0 * CW + c;
                    const float* b1p = Ms + (size_t)(r0 + 1) * CW + c;
#pragma unroll
                    for (int p = 0; p < 4; p++) {
                        x00 += b0p[p * PS]; x01 += b0p[p * PS + 1];
                        x10 += b1p[p * PS]; x11 += b1p[p * PS + 1];
                    }
                }
            }
            *reinterpret_cast<ull*>(outp + (size_t)r0 * CW + c) = pack2(x00, x01);
            *reinterpret_cast<ull*>(outp + (size_t)(r0 + 1) * CW + c) = pack2(x10, x11);
        }
    }
}

// Materialize dense B^1024 (-> g_Ba) and dense X (-> g_Xb) from buf 0 partials
__global__ void k_sumXB() {
    int i = blockIdx.x * 256 + threadIdx.x;
    if (i >= MS * CW) return;
    const int PS = MS * CW;
    const float* Ms = g_M[0][0];
    float s = Ms[i] + Ms[i + PS] + Ms[i + 2 * PS] + Ms[i + 3 * PS];
    int r = i / CW, c = i - r * CW;
    if (c < MS) g_Ba[(size_t)r * MS + c] = s;
    else g_Xb[r * NRHS + (c - MS)] = s;
}

// Final factor: Xa = Xb + B^1024 @ Xb
__global__ void k_xonly() {
    int idx = blockIdx.x * blockDim.x + threadIdx.x;
    if (idx >= MS * NRHS) return;
    int j = idx >> 4, c = idx & 15;
    const float* br = g_Ba + (size_t)j * MS;
    float s = g_Xb[idx];
#pragma unroll 4
    for (int k = 0; k < MS; k++) s = fmaf(br[k], g_Xb[k * NRHS + c], s);
    g_Xa[idx] = s;
}

// w[c][d] = (1/b) * sum_j Xa[j][c] * K[j][d]
__global__ void k_w() {
    int idx = blockIdx.x * 256 + threadIdx.x;
    if (idx >= NRHS * DF) return;
    int c = idx / DF, d = idx - c * DF;
    float s = 0.f;
#pragma unroll 4
    for (int j = 0; j < MS; j++) s = fmaf(g_Xa[j * NRHS + c], g_KF[(size_t)j * DF + d], s);
    g_w[idx] = s * g_scal[1];
}

// logits[q][c] = -gamma * sum_d f_x[q][d] * w[c][d]
__global__ void k_logits(float* __restrict__ out, const float* __restrict__ gamma) {
    int idx = blockIdx.x * 256 + threadIdx.x;
    if (idx >= MQ * 16) return;
    int q = idx >> 4, c = idx & 15;
    const float4* f = reinterpret_cast<const float4*>(g_KF + (size_t)(MS + q) * DF);
    const float4* wr = reinterpret_cast<const float4*>(g_w + (size_t)c * DF);
    float s = 0.f;
#pragma unroll 4
    for (int d = 0; d < DF / 4; d++) {
        float4 a = f[d], b = wr[d];
        s = fmaf(a.x, b.x, s); s = fmaf(a.y, b.y, s);
        s = fmaf(a.z, b.z, s); s = fmaf(a.w, b.w, s);
    }
    out[idx] = -gamma[0] * s;
}

// ============================================================
extern "C" void kernel_launch(void* const* d_in, const int* in_sizes, int n_in,
                              void* d_out, int out_size) {
    const float* S = (const float*)d_in[0];
    const float* Qm = (const float*)d_in[1];
    const float* W = (const float*)d_in[2];
    const float* gamma = (const float*)d_in[3];
    float* out = (float*)d_out;
    (void)in_sizes; (void)n_in; (void)out_size;

    k_gemm_kf<<<dim3(10, 5, SPLITS_KF), 128>>>(S, Qm, W);
    k_reduce_kf<<<(MKF * DF + 255) / 256, 256>>>();
    k_gemm_aul<<<dim3(13, 7), 128>>>();
    k_gemm_a2<<<dim3(13, 7), 128>>>();
    k_f2_final<<<1, 128>>>();
    k_buildBX<<<(MS * MS + MS * NRHS + 255) / 256, 256>>>();
    // chain: 9 iterations; iter j applies (I + B^{2^j}) and squares B^{2^j}
    k_iter<<<dim3(13, 7, 4), 128>>>(1, 0, 0);
    int src = 0, dst = 1;
    for (int j = 2; j <= 9; j++) {
        k_iter<<<dim3(13, 7, 4), 128>>>(0, src, dst);
        int t = src; src = dst; dst = t;
    }
    // after 9 iters result buf = 0 (1->0 on even count of flips: dst of iter9 = 0)
    k_sumXB<<<(MS * CW + 255) / 256, 256>>>();
    k_xonly<<<(MS * NRHS + 255) / 256, 256>>>();
    k_w<<<(NRHS * DF + 255) / 256, 256>>>();
    k_logits<<<(MQ * 16 + 255) / 256, 256>>>(out, gamma);
}

// round 7
// speedup vs baseline: 1.5018x; 1.1499x over previous
#include <cuda_runtime.h>

typedef unsigned long long ull;

#define NSUP 25
#define CWH  3072
#define DF   640
#define MS   400
#define MQ   240
#define MKF  640
#define NRHS 16
#define CW   416          // concat width: 400 B cols + 16 X cols
#define SPLITS_KF 8
#define NRED 625

// ---------------- device scratch ----------------
__device__ __align__(16) float g_KF[MKF * DF];
__device__ __align__(16) float g_parts[SPLITS_KF * MKF * DF];  // kf partials, then aul partials
__device__ __align__(16) float g_aul[MS * MS];
__device__ __align__(16) float g_A2[MS * MS];
__device__ __align__(16) float g_Ba[MS * MS];      // dense B^512 at the end
__device__ __align__(16) float g_Bb[MS * MS];      // B^2
__device__ __align__(16) float g_Xa[MS * NRHS];
__device__ __align__(16) float g_Xb[MS * NRHS];
__device__ __align__(16) float g_M[2][4][MS * CW]; // chain ping/pong, 4 K-splits (also a2 partials in g_M[0])
__device__ float g_red[1024];
__device__ float g_scal[4];
__device__ __align__(16) float g_w[NRHS * DF];

// ---------------- packed f32x2 helpers ----------------
__device__ __forceinline__ ull ffma2(ull a, ull b, ull c) {
    ull d;
    asm("fma.rn.f32x2 %0, %1, %2, %3;" : "=l"(d) : "l"(a), "l"(b), "l"(c));
    return d;
}
union UF2 { float2 f; ull u; };
__device__ __forceinline__ ull pack2(float x, float y) {
    UF2 t; t.f = make_float2(x, y); return t.u;
}
__device__ __forceinline__ float2 u2f(ull v) { UF2 t; t.u = v; return t.f; }

// ============================================================
// GEMM KF: [S;Q](640x3072) @ W(3072x640) -> split-K partials
// ============================================================
__global__ __launch_bounds__(128) void k_gemm_kf(const float* __restrict__ S,
                                                 const float* __restrict__ Qm,
                                                 const float* __restrict__ W) {
    __shared__ float As[16][132];
    __shared__ float Bs[16][68];
    const int tid = threadIdx.x;
    const int n0 = blockIdx.x * 64;
    const int m0 = blockIdx.y * 128;
    const int sp = blockIdx.z;
    const int nkt = CWH / 16;
    const int kt0 = sp * nkt / SPLITS_KF, kt1 = (sp + 1) * nkt / SPLITS_KF;
    const int arow = m0 + tid;
    const float* Ap = (arow < MS) ? (S + (size_t)arow * CWH)
                                  : (Qm + (size_t)(arow - MS) * CWH);
    const int ty = tid >> 3, tx = tid & 7;
    ull acc[8][4];
#pragma unroll
    for (int i = 0; i < 8; i++)
#pragma unroll
        for (int u = 0; u < 4; u++) acc[i][u] = 0ull;

    for (int kt = kt0; kt < kt1; ++kt) {
        const int k0 = kt * 16;
#pragma unroll
        for (int q = 0; q < 4; q++) {
            float4 v = *reinterpret_cast<const float4*>(Ap + k0 + q * 4);
            As[q * 4 + 0][tid] = v.x; As[q * 4 + 1][tid] = v.y;
            As[q * 4 + 2][tid] = v.z; As[q * 4 + 3][tid] = v.w;
        }
#pragma unroll
        for (int i = 0; i < 2; i++) {
            int idx = tid + i * 128;
            int kk = idx >> 4, c4 = idx & 15;
            float4 v = *reinterpret_cast<const float4*>(W + (size_t)(k0 + kk) * DF + n0 + c4 * 4);
            *reinterpret_cast<float4*>(&Bs[kk][c4 * 4]) = v;
        }
        __syncthreads();
#pragma unroll
        for (int k = 0; k < 16; k++) {
            float av[8];
            *(float4*)&av[0] = *(float4*)&As[k][ty * 8];
            *(float4*)&av[4] = *(float4*)&As[k][ty * 8 + 4];
            ull bv[4];
#pragma unroll
            for (int u = 0; u < 4; u++)
                bv[u] = *reinterpret_cast<const ull*>(&Bs[k][tx * 8 + 2 * u]);
#pragma unroll
            for (int i = 0; i < 8; i++) {
                ull ai = pack2(av[i], av[i]);
#pragma unroll
                for (int u = 0; u < 4; u++) acc[i][u] = ffma2(ai, bv[u], acc[i][u]);
            }
        }
        __syncthreads();
    }
    float* out = g_parts + (size_t)sp * MKF * DF;
#pragma unroll
    for (int i = 0; i < 8; i++) {
        int r = m0 + ty * 8 + i;
#pragma unroll
        for (int u = 0; u < 4; u++)
            *reinterpret_cast<ull*>(out + (size_t)r * DF + n0 + tx * 8 + 2 * u) = acc[i][u];
    }
}

__global__ void k_reduce_kf() {
    int i = blockIdx.x * 256 + threadIdx.x;
    if (i >= MKF * DF) return;
    const size_t T = (size_t)MKF * DF;
    float s = 0.f;
#pragma unroll
    for (int p = 0; p < SPLITS_KF; p++) s += g_parts[p * T + i];
    g_KF[i] = s;
}

// ============================================================
// aul = K K^T (NT, 400x400x640) split-K=4 -> partials in g_parts
// grid (13,7,4), 128 thr, BM=64 BN=32
// ============================================================
__global__ __launch_bounds__(128) void k_gemm_aul() {
    __shared__ float As[16][68];
    __shared__ float Bs2[16][72];
    const int tid = threadIdx.x;
    const int n0 = blockIdx.x * 32;
    const int m0 = blockIdx.y * 64;
    const int sp = blockIdx.z;
    const int kt0 = sp * 10, kt1 = kt0 + 10;          // 40 kts / 4
    const int ty = tid >> 4, tx = tid & 15;
    ull acc[4][2];
#pragma unroll
    for (int i = 0; i < 4; i++) { acc[i][0] = 0ull; acc[i][1] = 0ull; }

    for (int kt = kt0; kt < kt1; ++kt) {
        const int k0 = kt * 16;
#pragma unroll
        for (int i = 0; i < 2; i++) {
            int idx = tid + i * 128;
            int r = idx >> 2, q = idx & 3;
            int rr = m0 + r; if (rr > MS - 1) rr = MS - 1;
            float4 v = *reinterpret_cast<const float4*>(g_KF + (size_t)rr * DF + k0 + q * 4);
            As[q * 4 + 0][r] = v.x; As[q * 4 + 1][r] = v.y;
            As[q * 4 + 2][r] = v.z; As[q * 4 + 3][r] = v.w;
        }
        {
            int n = tid >> 2, q = tid & 3;
            int nn = n0 + n; if (nn > MS - 1) nn = MS - 1;
            float4 v = *reinterpret_cast<const float4*>(g_KF + (size_t)nn * DF + k0 + q * 4);
            *reinterpret_cast<ull*>(&Bs2[q * 4 + 0][n * 2]) = pack2(v.x, v.x);
            *reinterpret_cast<ull*>(&Bs2[q * 4 + 1][n * 2]) = pack2(v.y, v.y);
            *reinterpret_cast<ull*>(&Bs2[q * 4 + 2][n * 2]) = pack2(v.z, v.z);
            *reinterpret_cast<ull*>(&Bs2[q * 4 + 3][n * 2]) = pack2(v.w, v.w);
        }
        __syncthreads();
#pragma unroll
        for (int k = 0; k < 16; k++) {
            float4 a0 = *(const float4*)&As[k][ty * 8];
            float4 a1 = *(const float4*)&As[k][ty * 8 + 4];
            float4 bq = *(const float4*)&Bs2[k][tx * 4];
            ull ap[4] = { pack2(a0.x, a0.y), pack2(a0.z, a0.w),
                          pack2(a1.x, a1.y), pack2(a1.z, a1.w) };
            ull b0 = pack2(bq.x, bq.y), b1 = pack2(bq.z, bq.w);
#pragma unroll
            for (int i = 0; i < 4; i++) {
                acc[i][0] = ffma2(ap[i], b0, acc[i][0]);
                acc[i][1] = ffma2(ap[i], b1, acc[i][1]);
            }
        }
        __syncthreads();
    }
    float* out = g_parts + (size_t)sp * MS * MS;
    int c = n0 + tx * 2;
    if (c < MS) {
#pragma unroll
        for (int i = 0; i < 4; i++) {
            int r0 = m0 + ty * 8 + 2 * i;
            if (r0 < MS) {
                float2 f0 = u2f(acc[i][0]);   // (o[r0][c], o[r0+1][c])
                float2 f1 = u2f(acc[i][1]);   // (o[r0][c+1], o[r0+1][c+1])
                *reinterpret_cast<ull*>(out + (size_t)r0 * MS + c) = pack2(f0.x, f1.x);
                *reinterpret_cast<ull*>(out + (size_t)(r0 + 1) * MS + c) = pack2(f0.y, f1.y);
            }
        }
    }
}

__global__ void k_red_aul() {
    int i = blockIdx.x * 256 + threadIdx.x;
    if (i >= MS * MS) return;
    const size_t T = (size_t)MS * MS;
    float s = g_parts[i] + g_parts[T + i] + g_parts[2 * T + i] + g_parts[3 * T + i];
    int r = i / MS, c = i - r * MS;
    if (r == c) s += 50.0f;
    g_aul[i] = s;
}

// ============================================================
// A2 = aul @ aul (NN, 400x400x400), split-K=4 -> partials in g_M[0]
// ============================================================
__global__ __launch_bounds__(128) void k_gemm_a2() {
    __shared__ float As[16][68];
    __shared__ float Bs2[16][72];
    const int tid = threadIdx.x;
    const int n0 = blockIdx.x * 32;
    const int m0 = blockIdx.y * 64;
    const int sp = blockIdx.z;
    const int kt0 = sp * 25 / 4, kt1 = (sp + 1) * 25 / 4;
    const int ty = tid >> 4, tx = tid & 15;
    ull acc[4][2];
#pragma unroll
    for (int i = 0; i < 4; i++) { acc[i][0] = 0ull; acc[i][1] = 0ull; }

    for (int kt = kt0; kt < kt1; ++kt) {
        const int k0 = kt * 16;
#pragma unroll
        for (int i = 0; i < 2; i++) {
            int idx = tid + i * 128;
            int r = idx >> 2, q = idx & 3;
            int rr = m0 + r; if (rr > MS - 1) rr = MS - 1;
            float4 v = *reinterpret_cast<const float4*>(g_aul + (size_t)rr * MS + k0 + q * 4);
            As[q * 4 + 0][r] = v.x; As[q * 4 + 1][r] = v.y;
            As[q * 4 + 2][r] = v.z; As[q * 4 + 3][r] = v.w;
        }
        {
            int kk = tid >> 3, c4 = tid & 7;
            int c = n0 + c4 * 4;
            float4 v = make_float4(0.f, 0.f, 0.f, 0.f);
            if (c < MS) v = *reinterpret_cast<const float4*>(g_aul + (size_t)(k0 + kk) * MS + c);
            *reinterpret_cast<float4*>(&Bs2[kk][c4 * 8]) = make_float4(v.x, v.x, v.y, v.y);
            *reinterpret_cast<float4*>(&Bs2[kk][c4 * 8 + 4]) = make_float4(v.z, v.z, v.w, v.w);
        }
        __syncthreads();
#pragma unroll
        for (int k = 0; k < 16; k++) {
            float4 a0 = *(const float4*)&As[k][ty * 8];
            float4 a1 = *(const float4*)&As[k][ty * 8 + 4];
            float4 bq = *(const float4*)&Bs2[k][tx * 4];
            ull ap[4] = { pack2(a0.x, a0.y), pack2(a0.z, a0.w),
                          pack2(a1.x, a1.y), pack2(a1.z, a1.w) };
            ull b0 = pack2(bq.x, bq.y), b1 = pack2(bq.z, bq.w);
#pragma unroll
            for (int i = 0; i < 4; i++) {
                acc[i][0] = ffma2(ap[i], b0, acc[i][0]);
                acc[i][1] = ffma2(ap[i], b1, acc[i][1]);
            }
        }
        __syncthreads();
    }
    float* out = g_M[0][sp];   // reuse chain buffer as a2 partial store
    int c = n0 + tx * 2;
    if (c < MS) {
#pragma unroll
        for (int i = 0; i < 4; i++) {
            int r0 = m0 + ty * 8 + 2 * i;
            if (r0 < MS) {
                float2 f0 = u2f(acc[i][0]);
                float2 f1 = u2f(acc[i][1]);
                *reinterpret_cast<ull*>(out + (size_t)r0 * MS + c) = pack2(f0.x, f1.x);
                *reinterpret_cast<ull*>(out + (size_t)(r0 + 1) * MS + c) = pack2(f0.y, f1.y);
            }
        }
    }
}

// Sum A2 partials -> g_A2 dense + per-block Frobenius^2 partial -> g_red
__global__ void k_fro() {
    int i = blockIdx.x * 256 + threadIdx.x;
    float v = 0.f;
    if (i < MS * MS) {
        v = g_M[0][0][i] + g_M[0][1][i] + g_M[0][2][i] + g_M[0][3][i];
        g_A2[i] = v;
    }
    __shared__ float sh[256];
    sh[threadIdx.x] = v * v; __syncthreads();
    for (int o = 128; o > 0; o >>= 1) {
        if (threadIdx.x < o) sh[threadIdx.x] += sh[threadIdx.x + o];
        __syncthreads();
    }
    if (threadIdx.x == 0) g_red[blockIdx.x] = sh[0];
}

// omega = 2/(b+50), b = ||A2||_F^(1/2); B^2 = I - 2wA + w^2 A2 ; X1 = 2P - w*rowblocksum(aul)
__global__ void k_buildBX() {
    __shared__ float sh[256];
    float t = 0.f;
    for (int i = threadIdx.x; i < NRED; i += 256) t += g_red[i];
    sh[threadIdx.x] = t; __syncthreads();
    for (int o = 128; o > 0; o >>= 1) {
        if (threadIdx.x < o) sh[threadIdx.x] += sh[threadIdx.x + o];
        __syncthreads();
    }
    float b = sqrtf(sqrtf(sh[0])) * 1.0001f;
    if (!(b > 51.f)) b = 51.f;
    float om = 2.0f / (b + 50.0f);
    if (blockIdx.x == 0 && threadIdx.x == 0) g_scal[1] = om;

    int i = blockIdx.x * 256 + threadIdx.x;
    if (i < MS * MS) {
        int r = i / MS, c = i - r * MS;
        float a = g_aul[i] * om;
        float a2 = g_A2[i] * om * om;
        float d = (r == c) ? 1.f : 0.f;
        g_Bb[i] = d - 2.f * a + a2;
    } else if (i < MS * MS + MS * NRHS) {
        int idx = i - MS * MS;
        int j = idx >> 4, c = idx & 15;
        float s = ((j / NSUP) == c) ? 2.f : 0.f;
        const float* row = g_aul + (size_t)j * MS + c * NSUP;
        float u = 0.f;
#pragma unroll
        for (int q = 0; q < NSUP; q++) u += row[q];
        g_Xa[idx] = s - u * om;
    }
}

// ============================================================
// Chain iteration, split-K=4, partial in / partial out.
// ============================================================
__global__ __launch_bounds__(128) void k_iter(int first, int src, int dst) {
    __shared__ float As[16][68];
    __shared__ float Bs2[16][72];
    const int tid = threadIdx.x;
    const int n0 = blockIdx.x * 32;
    const int m0 = blockIdx.y * 64;
    const int sp = blockIdx.z;
    const int kt0 = sp * 25 / 4, kt1 = (sp + 1) * 25 / 4;
    const int ty = tid >> 4, tx = tid & 15;
    const float* __restrict__ Ms = g_M[src][0];
    const int PS = MS * CW;
    ull acc[4][2];
#pragma unroll
    for (int i = 0; i < 4; i++) { acc[i][0] = 0ull; acc[i][1] = 0ull; }

    for (int kt = kt0; kt < kt1; ++kt) {
        const int k0 = kt * 16;
#pragma unroll
        for (int i = 0; i < 2; i++) {
            int idx = tid + i * 128;
            int r = idx >> 2, q = idx & 3;
            int rr = m0 + r; if (rr > MS - 1) rr = MS - 1;
            float4 v;
            if (first) {
                v = *reinterpret_cast<const float4*>(g_Bb + (size_t)rr * MS + k0 + q * 4);
            } else {
                const float* base = Ms + (size_t)rr * CW + k0 + q * 4;
                float4 v0 = *(const float4*)(base);
                float4 v1 = *(const float4*)(base + PS);
                float4 v2 = *(const float4*)(base + 2 * PS);
                float4 v3 = *(const float4*)(base + 3 * PS);
                v = make_float4(v0.x + v1.x + v2.x + v3.x, v0.y + v1.y + v2.y + v3.y,
                                v0.z + v1.z + v2.z + v3.z, v0.w + v1.w + v2.w + v3.w);
            }
            As[q * 4 + 0][r] = v.x; As[q * 4 + 1][r] = v.y;
            As[q * 4 + 2][r] = v.z; As[q * 4 + 3][r] = v.w;
        }
        {
            int kk = tid >> 3, c4 = tid & 7;
            int c = n0 + c4 * 4;
            int kr = k0 + kk;
            float4 v;
            if (first) {
                if (c < MS) v = *reinterpret_cast<const float4*>(g_Bb + (size_t)kr * MS + c);
                else        v = *reinterpret_cast<const float4*>(g_Xa + (size_t)kr * NRHS + (c - MS));
            } else {
                const float* base = Ms + (size_t)kr * CW + c;
                float4 v0 = *(const float4*)(base);
                float4 v1 = *(const float4*)(base + PS);
                float4 v2 = *(const float4*)(base + 2 * PS);
                float4 v3 = *(const float4*)(base + 3 * PS);
                v = make_float4(v0.x + v1.x + v2.x + v3.x, v0.y + v1.y + v2.y + v3.y,
                                v0.z + v1.z + v2.z + v3.z, v0.w + v1.w + v2.w + v3.w);
            }
            *reinterpret_cast<float4*>(&Bs2[kk][c4 * 8]) = make_float4(v.x, v.x, v.y, v.y);
            *reinterpret_cast<float4*>(&Bs2[kk][c4 * 8 + 4]) = make_float4(v.z, v.z, v.w, v.w);
        }
        __syncthreads();
#pragma unroll
        for (int k = 0; k < 16; k++) {
            float4 a0 = *(const float4*)&As[k][ty * 8];
            float4 a1 = *(const float4*)&As[k][ty * 8 + 4];
            float4 bq = *(const float4*)&Bs2[k][tx * 4];
            ull ap[4] = { pack2(a0.x, a0.y), pack2(a0.z, a0.w),
                          pack2(a1.x, a1.y), pack2(a1.z, a1.w) };
            ull b0 = pack2(bq.x, bq.y), b1 = pack2(bq.z, bq.w);
#pragma unroll
            for (int i = 0; i < 4; i++) {
                acc[i][0] = ffma2(ap[i], b0, acc[i][0]);
                acc[i][1] = ffma2(ap[i], b1, acc[i][1]);
            }
        }
        __syncthreads();
    }
    float* __restrict__ outp = g_M[dst][sp];
    int c = n0 + tx * 2;
#pragma unroll
    for (int i = 0; i < 4; i++) {
        int r0 = m0 + ty * 8 + 2 * i;
        if (r0 < MS) {
            float2 f0 = u2f(acc[i][0]);
            float2 f1 = u2f(acc[i][1]);
            float x00 = f0.x, x10 = f0.y, x01 = f1.x, x11 = f1.y;
            if (sp == 0 && c >= MS) {
                if (first) {
                    x00 += g_Xa[r0 * NRHS + (c - MS)];
                    x01 += g_Xa[r0 * NRHS + (c - MS) + 1];
                    x10 += g_Xa[(r0 + 1) * NRHS + (c - MS)];
                    x11 += g_Xa[(r0 + 1) * NRHS + (c - MS) + 1];
                } else {
                    const float* b0p = Ms + (size_t)r0 * CW + c;
                    const float* b1p = Ms + (size_t)(r0 + 1) * CW + c;
#pragma unroll
                    for (int p = 0; p < 4; p++) {
                        x00 += b0p[p * PS]; x01 += b0p[p * PS + 1];
                        x10 += b1p[p * PS]; x11 += b1p[p * PS + 1];
                    }
                }
            }
            *reinterpret_cast<ull*>(outp + (size_t)r0 * CW + c) = pack2(x00, x01);
            *reinterpret_cast<ull*>(outp + (size_t)(r0 + 1) * CW + c) = pack2(x10, x11);
        }
    }
}

// Materialize dense B^512 (-> g_Ba) and dense X (-> g_Xb) from buf-1 partials
__global__ void k_sumXB() {
    int i = blockIdx.x * 256 + threadIdx.x;
    if (i >= MS * CW) return;
    const int PS = MS * CW;
    const float* Ms = g_M[1][0];
    float s = Ms[i] + Ms[i + PS] + Ms[i + 2 * PS] + Ms[i + 3 * PS];
    int r = i / CW, c = i - r * CW;
    if (c < MS) g_Ba[(size_t)r * MS + c] = s;
    else g_Xb[r * NRHS + (c - MS)] = s;
}

// Final factor: Xa = Xb + B^512 @ Xb
__global__ void k_xonly() {
    int idx = blockIdx.x * blockDim.x + threadIdx.x;
    if (idx >= MS * NRHS) return;
    int j = idx >> 4, c = idx & 15;
    const float* br = g_Ba + (size_t)j * MS;
    float s = g_Xb[idx];
#pragma unroll 4
    for (int k = 0; k < MS; k++) s = fmaf(br[k], g_Xb[k * NRHS + c], s);
    g_Xa[idx] = s;
}

// w[c][d] = omega * sum_j Xa[j][c] * K[j][d]
__global__ void k_w() {
    int idx = blockIdx.x * 256 + threadIdx.x;
    if (idx >= NRHS * DF) return;
    int c = idx / DF, d = idx - c * DF;
    float s = 0.f;
#pragma unroll 4
    for (int j = 0; j < MS; j++) s = fmaf(g_Xa[j * NRHS + c], g_KF[(size_t)j * DF + d], s);
    g_w[idx] = s * g_scal[1];
}

// logits[q][c] = -gamma * sum_d f_x[q][d] * w[c][d]
__global__ void k_logits(float* __restrict__ out, const float* __restrict__ gamma) {
    int idx = blockIdx.x * 256 + threadIdx.x;
    if (idx >= MQ * 16) return;
    int q = idx >> 4, c = idx & 15;
    const float4* f = reinterpret_cast<const float4*>(g_KF + (size_t)(MS + q) * DF);
    const float4* wr = reinterpret_cast<const float4*>(g_w + (size_t)c * DF);
    float s = 0.f;
#pragma unroll 4
    for (int d = 0; d < DF / 4; d++) {
        float4 a = f[d], b = wr[d];
        s = fmaf(a.x, b.x, s); s = fmaf(a.y, b.y, s);
        s = fmaf(a.z, b.z, s); s = fmaf(a.w, b.w, s);
    }
    out[idx] = -gamma[0] * s;
}

// ============================================================
extern "C" void kernel_launch(void* const* d_in, const int* in_sizes, int n_in,
                              void* d_out, int out_size) {
    const float* S = (const float*)d_in[0];
    const float* Qm = (const float*)d_in[1];
    const float* W = (const float*)d_in[2];
    const float* gamma = (const float*)d_in[3];
    float* out = (float*)d_out;
    (void)in_sizes; (void)n_in; (void)out_size;

    k_gemm_kf<<<dim3(10, 5, SPLITS_KF), 128>>>(S, Qm, W);
    k_reduce_kf<<<(MKF * DF + 255) / 256, 256>>>();
    k_gemm_aul<<<dim3(13, 7, 4), 128>>>();
    k_red_aul<<<(MS * MS + 255) / 256, 256>>>();
    k_gemm_a2<<<dim3(13, 7, 4), 128>>>();
    k_fro<<<NRED, 256>>>();
    k_buildBX<<<(MS * MS + MS * NRHS + 255) / 256, 256>>>();
    // chain: 8 iterations with omega-scaling (1024 Neumann terms incl. final xonly)
    k_iter<<<dim3(13, 7, 4), 128>>>(1, 0, 0);
    int src = 0, dst = 1;
    for (int j = 2; j <= 8; j++) {
        k_iter<<<dim3(13, 7, 4), 128>>>(0, src, dst);
        int t = src; src = dst; dst = t;
    }
    // after 8 iters final partials live in g_M[1]
    k_sumXB<<<(MS * CW + 255) / 256, 256>>>();
    k_xonly<<<(MS * NRHS + 255) / 256, 256>>>();
    k_w<<<(NRHS * DF + 255) / 256, 256>>>();
    k_logits<<<(MQ * 16 + 255) / 256, 256>>>(out, gamma);
}